// round 3
// baseline (speedup 1.0000x reference)
#include <cuda_runtime.h>

// ---------------- problem constants ----------------
#define BB    4
#define DIM   64
#define RANK  32
#define EE    4
#define HH    256
#define WW    256
#define HWSZ  65536          // H*W = 2^16
#define NPIX  262144         // B*H*W

// ---------------- device scratch (no cudaMalloc allowed) ----------------
__device__ float g_gate[NPIX];
__device__ int   g_idx[NPIX];
__device__ float g_W[96 * 64];                    // fused [Wq(32x64); Wkv(64x64)]
__device__ float g_qpre [(size_t)NPIX * 32];
__device__ float g_kvpre[(size_t)NPIX * 64];
__device__ float g_q    [(size_t)NPIX * 32];
__device__ float g_k    [(size_t)NPIX * 32];
__device__ float g_v    [(size_t)NPIX * 32];
__device__ float g_attn [(size_t)NPIX * 32];
__device__ float g_comb [(size_t)NPIX * 64];

// ---------------- router: softmax + top1, zero combined ----------------
__global__ void k_router(const float* __restrict__ x,
                         const float* __restrict__ rw,
                         const float* __restrict__ rb) {
    int p = blockIdx.x * blockDim.x + threadIdx.x;
    if (p >= NPIX) return;
    int b = p >> 16, s = p & 0xFFFF;
    const float* xb = x + ((size_t)b * DIM) * HWSZ + s;
    float l0 = rb[0], l1 = rb[1], l2 = rb[2], l3 = rb[3];
    #pragma unroll 4
    for (int c = 0; c < 64; c++) {
        float xv = xb[(size_t)c * HWSZ];
        l0 += rw[c] * xv;
        l1 += rw[64 + c] * xv;
        l2 += rw[128 + c] * xv;
        l3 += rw[192 + c] * xv;
    }
    float lm = l0; int am = 0;
    if (l1 > lm) { lm = l1; am = 1; }
    if (l2 > lm) { lm = l2; am = 2; }
    if (l3 > lm) { lm = l3; am = 3; }
    float sum = expf(l0 - lm) + expf(l1 - lm) + expf(l2 - lm) + expf(l3 - lm);
    g_gate[p] = 1.0f / sum;   // softmax value at the argmax
    g_idx[p]  = am;
    // zero combined
    float* cb = g_comb + ((size_t)b * DIM) * HWSZ + s;
    #pragma unroll 4
    for (int c = 0; c < 64; c++) cb[(size_t)c * HWSZ] = 0.f;
}

// ---------------- fold q_w@p0_w and kv_w@p0_w ----------------
__global__ void k_prep(const float* __restrict__ qw,   // (32,32)
                       const float* __restrict__ kvw,  // (64,32)
                       const float* __restrict__ p0) { // (32,64)
    int i = blockIdx.x * blockDim.x + threadIdx.x;
    if (i >= 96 * 64) return;
    int o = i >> 6, c = i & 63;
    float acc = 0.f;
    if (o < 32) {
        #pragma unroll
        for (int r = 0; r < 32; r++) acc += qw[o * 32 + r] * p0[r * 64 + c];
    } else {
        int oo = o - 32;
        #pragma unroll
        for (int r = 0; r < 32; r++) acc += kvw[oo * 32 + r] * p0[r * 64 + c];
    }
    g_W[i] = acc;
}

// ---------------- A: fused masked 1x1 convs -> qpre(32), kvpre(64) ----------------
__global__ __launch_bounds__(128) void k_A(const float* __restrict__ x, int e) {
    __shared__ float sW[96 * 64];
    int tid = threadIdx.x;
    for (int i = tid; i < 96 * 64; i += 128) sW[i] = g_W[i];
    __syncthreads();
    int p = blockIdx.x * 128 + tid;
    int b = p >> 16, s = p & 0xFFFF;
    float* qp = g_qpre  + ((size_t)b * 32) * HWSZ + s;
    float* kp = g_kvpre + ((size_t)b * 64) * HWSZ + s;
    float m = (g_idx[p] == e) ? g_gate[p] : 0.f;
    if (m == 0.f) {
        #pragma unroll 1
        for (int o = 0; o < 32; o++) qp[(size_t)o * HWSZ] = 0.f;
        #pragma unroll 1
        for (int o = 0; o < 64; o++) kp[(size_t)o * HWSZ] = 0.f;
        return;
    }
    float xm[64];
    const float* xb = x + ((size_t)b * DIM) * HWSZ + s;
    #pragma unroll
    for (int c = 0; c < 64; c++) xm[c] = xb[(size_t)c * HWSZ] * m;
    #pragma unroll 1
    for (int o = 0; o < 32; o++) {
        float acc = 0.f;
        #pragma unroll
        for (int c = 0; c < 64; c++) acc += sW[o * 64 + c] * xm[c];
        qp[(size_t)o * HWSZ] = acc;
    }
    #pragma unroll 1
    for (int o = 0; o < 64; o++) {
        float acc = 0.f;
        #pragma unroll
        for (int c = 0; c < 64; c++) acc += sW[(32 + o) * 64 + c] * xm[c];
        kp[(size_t)o * HWSZ] = acc;
    }
}

// ---------------- depthwise conv, 16x16 tile + halo ----------------
template <int KS, int CH, bool SPLIT>
__global__ void k_dw(const float* __restrict__ in,
                     const float* __restrict__ wgt,
                     const float* __restrict__ bias,
                     float* __restrict__ outA,
                     float* __restrict__ outB) {
    constexpr int T = 16 + KS - 1;
    __shared__ float tile[T * T];
    __shared__ float sw[KS * KS];
    int c = blockIdx.z % CH, b = blockIdx.z / CH;
    const float* ip = in + (size_t)blockIdx.z * HWSZ;
    int tid = threadIdx.y * 16 + threadIdx.x;
    if (tid < KS * KS) sw[tid] = wgt[c * KS * KS + tid];
    int by0 = blockIdx.y * 16 - KS / 2;
    int bx0 = blockIdx.x * 16 - KS / 2;
    for (int i = tid; i < T * T; i += 256) {
        int ly = i / T, lx = i - ly * T;
        int gy = by0 + ly, gx = bx0 + lx;
        tile[i] = (gy >= 0 && gy < HH && gx >= 0 && gx < WW) ? ip[gy * WW + gx] : 0.f;
    }
    __syncthreads();
    float acc = bias[c];
    #pragma unroll
    for (int ky = 0; ky < KS; ky++)
        #pragma unroll
        for (int kx = 0; kx < KS; kx++)
            acc += sw[ky * KS + kx] * tile[(threadIdx.y + ky) * T + threadIdx.x + kx];
    int oy = blockIdx.y * 16 + threadIdx.y;
    int ox = blockIdx.x * 16 + threadIdx.x;
    float* op;
    if (SPLIT) {
        op = (c < CH / 2)
           ? outA + ((size_t)(b * (CH / 2) + c)) * HWSZ
           : outB + ((size_t)(b * (CH / 2) + c - CH / 2)) * HWSZ;
    } else {
        op = outA + (size_t)blockIdx.z * HWSZ;
    }
    op[oy * WW + ox] = acc;
}

// ---------------- patch attention: 8x8 circular conv(q,k) ----------------
__global__ __launch_bounds__(256) void k_attn() {
    __shared__ float sq[32][64];
    __shared__ float sk[32][64];
    int tid = threadIdx.x;
    int grp = tid >> 3, i = tid & 7;
    int g = blockIdx.x * 32 + grp;            // patch-channel id, 0..131071
    int plane = g >> 10;                      // b*32 + c
    int sp = g & 1023;
    int ph = sp >> 5, pw = sp & 31;
    size_t base = (size_t)plane * HWSZ + (ph * 8) * WW + pw * 8;
    const float* qp = g_q + base;
    const float* kp = g_k + base;
    #pragma unroll
    for (int j = 0; j < 8; j++) {
        sq[grp][i * 8 + j] = qp[i * WW + j];
        sk[grp][i * 8 + j] = kp[i * WW + j];
    }
    __syncthreads();
    const float* q = sq[grp];
    const float* k = sk[grp];
    float out[8] = {0, 0, 0, 0, 0, 0, 0, 0};
    #pragma unroll
    for (int a = 0; a < 8; a++) {
        int ia = (i - a) & 7;
        float kr[8];
        #pragma unroll
        for (int t = 0; t < 8; t++) kr[t] = k[ia * 8 + t];
        #pragma unroll
        for (int bb = 0; bb < 8; bb++) {
            float qv = q[a * 8 + bb];
            #pragma unroll
            for (int j = 0; j < 8; j++) out[j] += qv * kr[(j - bb) & 7];
        }
    }
    float* op = g_attn + (size_t)plane * HWSZ + (ph * 8 + i) * WW + pw * 8;
    #pragma unroll
    for (int j = 0; j < 8; j++) op[j] = out[j];
}

// ---------------- fused epilogue: LN, *v, fp, gate, p2, combine ----------------
__global__ __launch_bounds__(128) void k_D(const float* __restrict__ x,
                                           const float* __restrict__ sh,
                                           const float* __restrict__ fpw,
                                           const float* __restrict__ fpb,
                                           const float* __restrict__ p1w,
                                           const float* __restrict__ p2w,
                                           const float* __restrict__ lnw,
                                           const float* __restrict__ lnb,
                                           int e) {
    __shared__ float s_fp[32 * 32];
    __shared__ float s_p1[32 * 64];
    __shared__ float s_p2[64 * 32];
    __shared__ float s_fpb[32], s_lnw[32], s_lnb[32];
    int tid = threadIdx.x;
    for (int i = tid; i < 1024; i += 128) s_fp[i] = fpw[i];
    for (int i = tid; i < 2048; i += 128) s_p1[i] = p1w[i];
    for (int i = tid; i < 2048; i += 128) s_p2[i] = p2w[i];
    if (tid < 32) { s_fpb[tid] = fpb[tid]; s_lnw[tid] = lnw[tid]; s_lnb[tid] = lnb[tid]; }
    __syncthreads();

    int p = blockIdx.x * 128 + tid;
    int b = p >> 16, s = p & 0xFFFF;
    float m = (g_idx[p] == e) ? g_gate[p] : 0.f;
    if (m == 0.f) return;

    // gate path: gacc[o] = p1 @ shared
    float gacc[32];
    #pragma unroll
    for (int o = 0; o < 32; o++) gacc[o] = 0.f;
    const float* shb = sh + ((size_t)b * DIM) * HWSZ + s;
    #pragma unroll 1
    for (int c = 0; c < 64; c++) {
        float shv = shb[(size_t)c * HWSZ];
        #pragma unroll
        for (int o = 0; o < 32; o++) gacc[o] += s_p1[o * 64 + c] * shv;
    }

    // LN over channels of attn, multiply v
    const float* ap = g_attn + ((size_t)b * 32) * HWSZ + s;
    const float* vp = g_v    + ((size_t)b * 32) * HWSZ + s;
    float t[32];
    float sum = 0.f, sq = 0.f;
    #pragma unroll
    for (int r = 0; r < 32; r++) {
        t[r] = ap[(size_t)r * HWSZ];
        sum += t[r];
        sq  += t[r] * t[r];
    }
    float mean = sum * (1.f / 32.f);
    float var  = sq * (1.f / 32.f) - mean * mean;
    float inv  = rsqrtf(var + 1e-5f);
    #pragma unroll
    for (int r = 0; r < 32; r++)
        t[r] = ((t[r] - mean) * inv * s_lnw[r] + s_lnb[r]) * vp[(size_t)r * HWSZ];

    // body*gate
    float bg[32];
    #pragma unroll
    for (int o = 0; o < 32; o++) {
        float acc = s_fpb[o];
        #pragma unroll
        for (int r = 0; r < 32; r++) acc += s_fp[o * 32 + r] * t[r];
        float z = m * gacc[o];
        float sg = z / (1.f + expf(-z));
        bg[o] = acc * sg;
    }

    // p2 projection + residual, scaled by m
    const float* xb = x + ((size_t)b * DIM) * HWSZ + s;
    float* cb = g_comb + ((size_t)b * DIM) * HWSZ + s;
    float m2 = m * m;
    #pragma unroll 1
    for (int oc = 0; oc < 64; oc++) {
        float acc = 0.f;
        #pragma unroll
        for (int r = 0; r < 32; r++) acc += s_p2[oc * 32 + r] * bg[r];
        cb[(size_t)oc * HWSZ] = m * acc + m2 * xb[(size_t)oc * HWSZ];
    }
}

// ---------------- final 64x64 output conv ----------------
__global__ __launch_bounds__(128) void k_out(const float* __restrict__ ow,
                                             const float* __restrict__ ob,
                                             float* __restrict__ out) {
    __shared__ float sW[64 * 64];
    __shared__ float sB[64];
    int tid = threadIdx.x;
    for (int i = tid; i < 4096; i += 128) sW[i] = ow[i];
    if (tid < 64) sB[tid] = ob[tid];
    __syncthreads();
    int p = blockIdx.x * 128 + tid;
    int b = p >> 16, s = p & 0xFFFF;
    const float* cb = g_comb + ((size_t)b * DIM) * HWSZ + s;
    float cv[64];
    #pragma unroll
    for (int c = 0; c < 64; c++) cv[c] = cb[(size_t)c * HWSZ];
    float* ob_ = out + ((size_t)b * DIM) * HWSZ + s;
    #pragma unroll 1
    for (int o = 0; o < 64; o++) {
        float acc = sB[o];
        #pragma unroll
        for (int c = 0; c < 64; c++) acc += sW[o * 64 + c] * cv[c];
        ob_[(size_t)o * HWSZ] = acc;
    }
}

// ---------------- launch ----------------
extern "C" void kernel_launch(void* const* d_in, const int* in_sizes, int n_in,
                              void* d_out, int out_size) {
    const float* x     = (const float*)d_in[0];
    const float* sh    = (const float*)d_in[1];
    const float* rw    = (const float*)d_in[2];
    const float* rb    = (const float*)d_in[3];
    const float* p0w   = (const float*)d_in[4];
    const float* p1w   = (const float*)d_in[5];
    const float* p2w   = (const float*)d_in[6];
    const float* qw    = (const float*)d_in[7];
    const float* qdww  = (const float*)d_in[8];
    const float* qdwb  = (const float*)d_in[9];
    const float* kvw   = (const float*)d_in[10];
    const float* kvdww = (const float*)d_in[11];
    const float* kvdwb = (const float*)d_in[12];
    const float* lnw   = (const float*)d_in[13];
    const float* lnb   = (const float*)d_in[14];
    const float* fpw   = (const float*)d_in[15];
    const float* fpb   = (const float*)d_in[16];
    const float* outw  = (const float*)d_in[17];
    const float* outb  = (const float*)d_in[18];
    float* out = (float*)d_out;

    k_router<<<NPIX / 128, 128>>>(x, rw, rb);

    for (int e = 0; e < EE; e++) {
        k_prep<<<(96 * 64 + 255) / 256, 256>>>(qw + e * 32 * 32,
                                               kvw + e * 64 * 32,
                                               p0w + e * 32 * 64);
        k_A<<<NPIX / 128, 128>>>(x, e);

        dim3 blk(16, 16);
        dim3 g3(WW / 16, HH / 16, BB * 32);
        k_dw<3, 32, false><<<g3, blk>>>(g_qpre, qdww + e * 32 * 9, qdwb + e * 32,
                                        g_q, nullptr);
        dim3 g7(WW / 16, HH / 16, BB * 64);
        k_dw<7, 64, true><<<g7, blk>>>(g_kvpre, kvdww + e * 64 * 49, kvdwb + e * 64,
                                       g_k, g_v);

        k_attn<<<(BB * 32 * 32 * 32) / 32, 256>>>();

        k_D<<<NPIX / 128, 128>>>(x, sh,
                                 fpw + e * 32 * 32, fpb + e * 32,
                                 p1w + e * 32 * 64, p2w + e * 64 * 32,
                                 lnw + e * 32, lnb + e * 32, e);
    }

    k_out<<<NPIX / 128, 128>>>(outw, outb, out);
}

// round 4
// speedup vs baseline: 1.0010x; 1.0010x over previous
#include <cuda_runtime.h>

// ---------------- problem constants ----------------
#define BB    4
#define DIM   64
#define RANK  32
#define EE    4
#define HH    256
#define WW    256
#define HWSZ  65536          // H*W = 2^16
#define NPIX  262144         // B*H*W

// ---------------- device scratch (no cudaMalloc allowed) ----------------
__device__ float g_gate[NPIX];
__device__ int   g_idx[NPIX];
__device__ float g_W[4 * 96 * 64];                // fused [Wq;Wkv] per expert
__device__ float g_qpre [(size_t)NPIX * 32];
__device__ float g_kvpre[(size_t)NPIX * 64];
__device__ float g_q    [(size_t)NPIX * 32];      // per-expert, reused
__device__ float g_k    [(size_t)NPIX * 32];      // per-expert, reused
__device__ float g_v    [(size_t)NPIX * 32];      // dense (owned pixels accumulate over passes)
__device__ float g_attn [(size_t)NPIX * 32];      // dense (owned pixels)
__device__ float g_comb [(size_t)NPIX * 64];

// ---------------- router: softmax + top1 ----------------
__global__ __launch_bounds__(256) void k_router(const float* __restrict__ x,
                                                const float* __restrict__ rw,
                                                const float* __restrict__ rb) {
    int p = blockIdx.x * 256 + threadIdx.x;
    int b = p >> 16, s = p & 0xFFFF;
    const float* xb = x + ((size_t)b * DIM) * HWSZ + s;
    float l0 = rb[0], l1 = rb[1], l2 = rb[2], l3 = rb[3];
    #pragma unroll 8
    for (int c = 0; c < 64; c++) {
        float xv = xb[(size_t)c * HWSZ];
        l0 += rw[c] * xv;
        l1 += rw[64 + c] * xv;
        l2 += rw[128 + c] * xv;
        l3 += rw[192 + c] * xv;
    }
    float lm = l0; int am = 0;
    if (l1 > lm) { lm = l1; am = 1; }
    if (l2 > lm) { lm = l2; am = 2; }
    if (l3 > lm) { lm = l3; am = 3; }
    float sum = expf(l0 - lm) + expf(l1 - lm) + expf(l2 - lm) + expf(l3 - lm);
    g_gate[p] = 1.0f / sum;
    g_idx[p]  = am;
}

// ---------------- fold q_w@p0_w / kv_w@p0_w for ALL experts ----------------
__global__ void k_prep(const float* __restrict__ qw,   // (E,32,32)
                       const float* __restrict__ kvw,  // (E,64,32)
                       const float* __restrict__ p0) { // (E,32,64)
    int i = blockIdx.x * blockDim.x + threadIdx.x;    // < 4*96*64
    int e = i / 6144;
    int rem = i - e * 6144;
    int o = rem >> 6, c = rem & 63;
    const float* p0e = p0 + e * 2048;
    float acc = 0.f;
    if (o < 32) {
        const float* qe = qw + e * 1024 + o * 32;
        #pragma unroll
        for (int r = 0; r < 32; r++) acc += qe[r] * p0e[r * 64 + c];
    } else {
        const float* ke = kvw + e * 2048 + (o - 32) * 32;
        #pragma unroll
        for (int r = 0; r < 32; r++) acc += ke[r] * p0e[r * 64 + c];
    }
    g_W[i] = acc;
}

// ---------------- A: dense fused 1x1 conv (per-pixel expert weights) ----------------
__global__ __launch_bounds__(256) void k_A(const float* __restrict__ x) {
    extern __shared__ float sW[];                     // 4*96*64
    int tid = threadIdx.x;
    for (int i = tid; i < 4 * 6144; i += 256) sW[i] = g_W[i];
    __syncthreads();
    int p = blockIdx.x * 256 + tid;
    int b = p >> 16, s = p & 0xFFFF;
    int e = g_idx[p];
    float m = g_gate[p];
    float xm[64];
    const float* xb = x + ((size_t)b * DIM) * HWSZ + s;
    #pragma unroll
    for (int c = 0; c < 64; c++) xm[c] = xb[(size_t)c * HWSZ] * m;
    const float4* Wv = (const float4*)(sW + e * 6144);
    float* qp = g_qpre  + ((size_t)b * 32) * HWSZ + s;
    float* kp = g_kvpre + ((size_t)b * 64) * HWSZ + s;
    #pragma unroll 2
    for (int o = 0; o < 32; o++) {
        const float4* wr = Wv + o * 16;
        float acc = 0.f;
        #pragma unroll
        for (int j = 0; j < 16; j++) {
            float4 w = wr[j];
            acc += w.x * xm[4 * j] + w.y * xm[4 * j + 1] + w.z * xm[4 * j + 2] + w.w * xm[4 * j + 3];
        }
        qp[(size_t)o * HWSZ] = acc;
    }
    #pragma unroll 2
    for (int o = 0; o < 64; o++) {
        const float4* wr = Wv + (32 + o) * 16;
        float acc = 0.f;
        #pragma unroll
        for (int j = 0; j < 16; j++) {
            float4 w = wr[j];
            acc += w.x * xm[4 * j] + w.y * xm[4 * j + 1] + w.z * xm[4 * j + 2] + w.w * xm[4 * j + 3];
        }
        kp[(size_t)o * HWSZ] = acc;
    }
}

// ---------------- masked depthwise conv, 32x32 tile, 4 outputs/thread ----------------
template <int KS, int CH, bool SPLIT>
__global__ __launch_bounds__(256) void k_dw(const float* __restrict__ in,
                                            const float* __restrict__ wgt,
                                            const float* __restrict__ bias,
                                            float* __restrict__ outA,
                                            float* __restrict__ outB,
                                            int e) {
    constexpr int T = 32 + KS - 1;
    __shared__ float tile[T * T];
    __shared__ float sw[KS * KS];
    int z = blockIdx.z;
    int c = z % CH, b = z / CH;
    const float* ip  = in + (size_t)z * HWSZ;
    const int*   idp = g_idx + (size_t)b * HWSZ;
    int tid = threadIdx.x;
    if (tid < KS * KS) sw[tid] = wgt[c * KS * KS + tid];
    int by0 = blockIdx.y * 32 - KS / 2;
    int bx0 = blockIdx.x * 32 - KS / 2;
    int flag = 0;
    for (int i = tid; i < T * T; i += 256) {
        int ly = i / T, lx = i - ly * T;
        int gy = by0 + ly, gx = bx0 + lx;
        float v = 0.f;
        if (gy >= 0 && gy < HH && gx >= 0 && gx < WW) {
            int off = gy * WW + gx;
            if (idp[off] == e) { v = ip[off]; flag = 1; }
        }
        tile[i] = v;
    }
    int any = __syncthreads_or(flag);
    int r  = tid >> 3;              // output row 0..31
    int c4 = (tid & 7) * 4;         // output col base
    int oy = blockIdx.y * 32 + r;
    int ox = blockIdx.x * 32 + c4;
    float bv = bias[c];
    float o0 = bv, o1 = bv, o2 = bv, o3 = bv;
    if (any) {
        #pragma unroll
        for (int ky = 0; ky < KS; ky++) {
            float row[KS + 3];
            const float* tr = tile + (r + ky) * T + c4;
            #pragma unroll
            for (int j = 0; j < KS + 3; j++) row[j] = tr[j];
            #pragma unroll
            for (int kx = 0; kx < KS; kx++) {
                float w = sw[ky * KS + kx];
                o0 += w * row[kx];
                o1 += w * row[kx + 1];
                o2 += w * row[kx + 2];
                o3 += w * row[kx + 3];
            }
        }
    }
    int oo = oy * WW + ox;
    if (!SPLIT || c < CH / 2) {
        float* op = SPLIT ? (outA + ((size_t)(b * (CH / 2) + c)) * HWSZ)
                          : (outA + (size_t)z * HWSZ);
        op[oo] = o0; op[oo + 1] = o1; op[oo + 2] = o2; op[oo + 3] = o3;
    } else {
        // v channels: only owned pixels are ever consumed -> write dense field
        float* op = outB + ((size_t)(b * (CH / 2) + (c - CH / 2))) * HWSZ;
        if (idp[oo]     == e) op[oo]     = o0;
        if (idp[oo + 1] == e) op[oo + 1] = o1;
        if (idp[oo + 2] == e) op[oo + 2] = o2;
        if (idp[oo + 3] == e) op[oo + 3] = o3;
    }
}

// ---------------- patch attention: 8x8 circular conv(q,k), one patch/block ----------------
__global__ __launch_bounds__(256) void k_attn(int e) {
    __shared__ float sq[32 * 64];
    __shared__ float sk[32 * 64];
    __shared__ int sowned[64];
    int blk = blockIdx.x;                 // B*1024 patches
    int b = blk >> 10;
    int sp = blk & 1023;
    int ph = sp >> 5, pw = sp & 31;
    int tid = threadIdx.x;
    int f = 0;
    if (tid < 64) {
        int py = ph * 8 + (tid >> 3), px = pw * 8 + (tid & 7);
        int o = (g_idx[b * HWSZ + py * WW + px] == e) ? 1 : 0;
        sowned[tid] = o;
        f = o;
    }
    int any = __syncthreads_or(f);
    if (!any) return;

    int ch = tid >> 3, i = tid & 7;
    int plane = b * 32 + ch;
    size_t base = (size_t)plane * HWSZ + (ph * 8 + i) * WW + pw * 8;
    const float* qp = g_q + base;
    const float* kp = g_k + base;
    #pragma unroll
    for (int j = 0; j < 8; j++) {
        sq[ch * 64 + i * 8 + j] = qp[j];
        sk[ch * 64 + i * 8 + j] = kp[j];
    }
    __syncthreads();

    const float* q = sq + ch * 64;
    const float* k = sk + ch * 64;
    float out[8] = {0, 0, 0, 0, 0, 0, 0, 0};
    #pragma unroll
    for (int a = 0; a < 8; a++) {
        int ia = (i - a) & 7;
        float kr[8];
        #pragma unroll
        for (int t = 0; t < 8; t++) kr[t] = k[ia * 8 + t];
        #pragma unroll
        for (int bb = 0; bb < 8; bb++) {
            float qv = q[a * 8 + bb];
            #pragma unroll
            for (int j = 0; j < 8; j++) out[j] += qv * kr[(j - bb) & 7];
        }
    }
    float* op = g_attn + base;
    #pragma unroll
    for (int j = 0; j < 8; j++)
        if (sowned[i * 8 + j]) op[j] = out[j];
}

// ---------------- fused epilogue, ONE dense pass (per-pixel expert weights) ----------------
__global__ __launch_bounds__(128) void k_D(const float* __restrict__ x,
                                           const float* __restrict__ sh,
                                           const float* __restrict__ fpw,
                                           const float* __restrict__ fpb,
                                           const float* __restrict__ p1w,
                                           const float* __restrict__ p2w,
                                           const float* __restrict__ lnw,
                                           const float* __restrict__ lnb) {
    extern __shared__ float sm[];   // per expert: fp 1024 | p1 2048 | p2 2048 | fpb 32 | lnw 32 | lnb 32 = 5216
    int tid = threadIdx.x;
    for (int i = tid; i < 4096; i += 128) sm[(i >> 10) * 5216 + (i & 1023)] = fpw[i];
    for (int i = tid; i < 8192; i += 128) sm[(i >> 11) * 5216 + 1024 + (i & 2047)] = p1w[i];
    for (int i = tid; i < 8192; i += 128) sm[(i >> 11) * 5216 + 3072 + (i & 2047)] = p2w[i];
    if (tid < 128) {
        sm[(tid >> 5) * 5216 + 5120 + (tid & 31)] = fpb[tid];
        sm[(tid >> 5) * 5216 + 5152 + (tid & 31)] = lnw[tid];
        sm[(tid >> 5) * 5216 + 5184 + (tid & 31)] = lnb[tid];
    }
    __syncthreads();

    int p = blockIdx.x * 128 + tid;
    int b = p >> 16, s = p & 0xFFFF;
    int e = g_idx[p];
    float m = g_gate[p];
    const float* base_ = sm + e * 5216;
    const float* s_fp  = base_;
    const float* s_p1  = base_ + 1024;
    const float* s_p2  = base_ + 3072;
    const float* s_fpb = base_ + 5120;
    const float* s_lnw = base_ + 5152;
    const float* s_lnb = base_ + 5184;

    // shared-path activations into registers
    float shv[64];
    const float* shb = sh + ((size_t)b * DIM) * HWSZ + s;
    #pragma unroll
    for (int c = 0; c < 64; c++) shv[c] = shb[(size_t)c * HWSZ];

    // LayerNorm(attn) * v
    const float* ap = g_attn + ((size_t)b * 32) * HWSZ + s;
    const float* vp = g_v    + ((size_t)b * 32) * HWSZ + s;
    float t[32];
    float sum = 0.f, sq = 0.f;
    #pragma unroll
    for (int r = 0; r < 32; r++) {
        t[r] = ap[(size_t)r * HWSZ];
        sum += t[r];
        sq  += t[r] * t[r];
    }
    float mean = sum * (1.f / 32.f);
    float var  = sq * (1.f / 32.f) - mean * mean;
    float inv  = rsqrtf(var + 1e-5f);
    #pragma unroll
    for (int r = 0; r < 32; r++)
        t[r] = ((t[r] - mean) * inv * s_lnw[r] + s_lnb[r]) * vp[(size_t)r * HWSZ];

    // per-o: fp dot + silu gate
    float bg[32];
    #pragma unroll 2
    for (int o = 0; o < 32; o++) {
        const float4* fr = (const float4*)(s_fp + o * 32);
        float acc = s_fpb[o];
        #pragma unroll
        for (int j = 0; j < 8; j++) {
            float4 w = fr[j];
            acc += w.x * t[4 * j] + w.y * t[4 * j + 1] + w.z * t[4 * j + 2] + w.w * t[4 * j + 3];
        }
        const float4* pr = (const float4*)(s_p1 + o * 64);
        float g = 0.f;
        #pragma unroll
        for (int j = 0; j < 16; j++) {
            float4 w = pr[j];
            g += w.x * shv[4 * j] + w.y * shv[4 * j + 1] + w.z * shv[4 * j + 2] + w.w * shv[4 * j + 3];
        }
        float z = m * g;
        float sg = z / (1.f + expf(-z));
        bg[o] = acc * sg;
    }

    // p2 projection + residual, scaled by m
    const float* xb = x + ((size_t)b * DIM) * HWSZ + s;
    float* cb = g_comb + ((size_t)b * DIM) * HWSZ + s;
    float m2 = m * m;
    #pragma unroll 2
    for (int oc = 0; oc < 64; oc++) {
        const float4* pr = (const float4*)(s_p2 + oc * 32);
        float acc = 0.f;
        #pragma unroll
        for (int j = 0; j < 8; j++) {
            float4 w = pr[j];
            acc += w.x * bg[4 * j] + w.y * bg[4 * j + 1] + w.z * bg[4 * j + 2] + w.w * bg[4 * j + 3];
        }
        cb[(size_t)oc * HWSZ] = m * acc + m2 * xb[(size_t)oc * HWSZ];
    }
}

// ---------------- final 64x64 output conv ----------------
__global__ __launch_bounds__(128) void k_out(const float* __restrict__ ow,
                                             const float* __restrict__ ob,
                                             float* __restrict__ out) {
    __shared__ float sW[64 * 64];
    __shared__ float sB[64];
    int tid = threadIdx.x;
    for (int i = tid; i < 4096; i += 128) sW[i] = ow[i];
    if (tid < 64) sB[tid] = ob[tid];
    __syncthreads();
    int p = blockIdx.x * 128 + tid;
    int b = p >> 16, s = p & 0xFFFF;
    const float* cb = g_comb + ((size_t)b * DIM) * HWSZ + s;
    float cv[64];
    #pragma unroll
    for (int c = 0; c < 64; c++) cv[c] = cb[(size_t)c * HWSZ];
    float* ob_ = out + ((size_t)b * DIM) * HWSZ + s;
    #pragma unroll 2
    for (int o = 0; o < 64; o++) {
        const float4* wr = (const float4*)(sW + o * 64);
        float acc = sB[o];
        #pragma unroll
        for (int j = 0; j < 16; j++) {
            float4 w = wr[j];
            acc += w.x * cv[4 * j] + w.y * cv[4 * j + 1] + w.z * cv[4 * j + 2] + w.w * cv[4 * j + 3];
        }
        ob_[(size_t)o * HWSZ] = acc;
    }
}

// ---------------- launch ----------------
extern "C" void kernel_launch(void* const* d_in, const int* in_sizes, int n_in,
                              void* d_out, int out_size) {
    const float* x     = (const float*)d_in[0];
    const float* sh    = (const float*)d_in[1];
    const float* rw    = (const float*)d_in[2];
    const float* rb    = (const float*)d_in[3];
    const float* p0w   = (const float*)d_in[4];
    const float* p1w   = (const float*)d_in[5];
    const float* p2w   = (const float*)d_in[6];
    const float* qw    = (const float*)d_in[7];
    const float* qdww  = (const float*)d_in[8];
    const float* qdwb  = (const float*)d_in[9];
    const float* kvw   = (const float*)d_in[10];
    const float* kvdww = (const float*)d_in[11];
    const float* kvdwb = (const float*)d_in[12];
    const float* lnw   = (const float*)d_in[13];
    const float* lnb   = (const float*)d_in[14];
    const float* fpw   = (const float*)d_in[15];
    const float* fpb   = (const float*)d_in[16];
    const float* outw  = (const float*)d_in[17];
    const float* outb  = (const float*)d_in[18];
    float* out = (float*)d_out;

    cudaFuncSetAttribute(k_A, cudaFuncAttributeMaxDynamicSharedMemorySize, 4 * 6144 * 4);
    cudaFuncSetAttribute(k_D, cudaFuncAttributeMaxDynamicSharedMemorySize, 4 * 5216 * 4);

    k_router<<<NPIX / 256, 256>>>(x, rw, rb);
    k_prep<<<(4 * 96 * 64) / 256, 256>>>(qw, kvw, p0w);
    k_A<<<NPIX / 256, 256, 4 * 6144 * 4>>>(x);

    dim3 blk(256);
    for (int e = 0; e < EE; e++) {
        dim3 g3(WW / 32, HH / 32, BB * 32);
        k_dw<3, 32, false><<<g3, blk>>>(g_qpre, qdww + e * 32 * 9, qdwb + e * 32,
                                        g_q, nullptr, e);
        dim3 g7(WW / 32, HH / 32, BB * 64);
        k_dw<7, 64, true><<<g7, blk>>>(g_kvpre, kvdww + e * 64 * 49, kvdwb + e * 64,
                                       g_k, g_v, e);
        k_attn<<<BB * 1024, 256>>>(e);
    }

    k_D<<<NPIX / 128, 128, 4 * 5216 * 4>>>(x, sh, fpw, fpb, p1w, p2w, lnw, lnb);
    k_out<<<NPIX / 128, 128>>>(outw, outb, out);
}

// round 5
// speedup vs baseline: 2.4648x; 2.4623x over previous
#include <cuda_runtime.h>

// ---------------- problem constants ----------------
#define BB    4
#define DIM   64
#define RANK  32
#define EE    4
#define HH    256
#define WW    256
#define HWSZ  65536          // H*W
#define NPIX  262144         // B*H*W

// ---------------- device scratch ----------------
__device__ float g_gate[NPIX];
__device__ int   g_idx[NPIX];
__device__ float g_W[4 * 96 * 64];                 // fused [Wq;Wkv] per expert
__device__ float g_pre[(size_t)NPIX * 96];         // pixel-major: [p][0:32)=qpre, [32:96)=kvpre
__device__ float g_av [(size_t)NPIX * 64];         // pixel-major: [p][0:32)=attn, [32:64)=v
__device__ float g_comb[(size_t)NPIX * 64];        // pixel-major

// ---------------- router ----------------
__global__ __launch_bounds__(256) void k_router(const float* __restrict__ x,
                                                const float* __restrict__ rw,
                                                const float* __restrict__ rb) {
    int p = blockIdx.x * 256 + threadIdx.x;
    int b = p >> 16, s = p & 0xFFFF;
    const float* xb = x + ((size_t)b * DIM) * HWSZ + s;
    float l0 = rb[0], l1 = rb[1], l2 = rb[2], l3 = rb[3];
    #pragma unroll 8
    for (int c = 0; c < 64; c++) {
        float xv = xb[(size_t)c * HWSZ];
        l0 += rw[c] * xv;
        l1 += rw[64 + c] * xv;
        l2 += rw[128 + c] * xv;
        l3 += rw[192 + c] * xv;
    }
    float lm = l0; int am = 0;
    if (l1 > lm) { lm = l1; am = 1; }
    if (l2 > lm) { lm = l2; am = 2; }
    if (l3 > lm) { lm = l3; am = 3; }
    float sum = expf(l0 - lm) + expf(l1 - lm) + expf(l2 - lm) + expf(l3 - lm);
    g_gate[p] = 1.0f / sum;
    g_idx[p]  = am;
}

// ---------------- fold q_w@p0_w / kv_w@p0_w for all experts ----------------
__global__ void k_prep(const float* __restrict__ qw,   // (E,32,32)
                       const float* __restrict__ kvw,  // (E,64,32)
                       const float* __restrict__ p0) { // (E,32,64)
    int i = blockIdx.x * blockDim.x + threadIdx.x;     // < 4*96*64
    int e = i / 6144;
    int rem = i - e * 6144;
    int o = rem >> 6, c = rem & 63;
    const float* p0e = p0 + e * 2048;
    float acc = 0.f;
    if (o < 32) {
        const float* qe = qw + e * 1024 + o * 32;
        #pragma unroll
        for (int r = 0; r < 32; r++) acc += qe[r] * p0e[r * 64 + c];
    } else {
        const float* ke = kvw + e * 2048 + (o - 32) * 32;
        #pragma unroll
        for (int r = 0; r < 32; r++) acc += ke[r] * p0e[r * 64 + c];
    }
    g_W[i] = acc;
}

// ---------------- A: dense fused 1x1 conv -> g_pre[p][96] ----------------
__global__ __launch_bounds__(256) void k_A(const float* __restrict__ x) {
    extern __shared__ float sW[];                      // 4*6144
    int tid = threadIdx.x;
    for (int i = tid; i < 4 * 6144; i += 256) sW[i] = g_W[i];
    __syncthreads();
    int p = blockIdx.x * 256 + tid;
    int b = p >> 16, s = p & 0xFFFF;
    int e = g_idx[p];
    float m = g_gate[p];
    float xm[64];
    const float* xb = x + ((size_t)b * DIM) * HWSZ + s;
    #pragma unroll
    for (int c = 0; c < 64; c++) xm[c] = xb[(size_t)c * HWSZ] * m;
    const float4* Wv = (const float4*)(sW + e * 6144);
    float* op = g_pre + (size_t)p * 96;
    #pragma unroll 2
    for (int og = 0; og < 24; og++) {                  // groups of 4 outputs
        float r[4];
        #pragma unroll
        for (int u = 0; u < 4; u++) {
            const float4* wr = Wv + (og * 4 + u) * 16;
            float acc = 0.f;
            #pragma unroll
            for (int j = 0; j < 16; j++) {
                float4 w = wr[j];
                acc += w.x * xm[4*j] + w.y * xm[4*j+1] + w.z * xm[4*j+2] + w.w * xm[4*j+3];
            }
            r[u] = acc;
        }
        *(float4*)(op + og * 4) = make_float4(r[0], r[1], r[2], r[3]);
    }
}

// ---------------- B: fused masked dwconv(3,7) + patch circular conv ----------------
// one block per (b, 8x8 patch); 512 threads
#define OFF_KV   0                    // 196*64
#define OFF_QT   12544                // 100*32
#define OFF_QE   15744                // 4*32*65
#define OFF_KE   24064                // 4*32*65
#define OFF_OUT  32384                // 64*64
#define OFF_WKV  36480                // 64*49
#define OFF_WQ   39616                // 32*9
#define OFF_BKV  39904                // 64
#define OFF_BQ   39968                // 32
#define OFF_MASK 40000                // 196
#define OFF_IDX  40196                // 196 (int)
#define SMEM_B_FLOATS 40392

__global__ __launch_bounds__(512) void k_B(const float* __restrict__ qdww,
                                           const float* __restrict__ qdwb,
                                           const float* __restrict__ kvdww,
                                           const float* __restrict__ kvdwb) {
    extern __shared__ float sm[];
    int* s_idxI = (int*)(sm + OFF_IDX);
    int tid = threadIdx.x;
    int blk = blockIdx.x;
    int b = blk >> 10, sp = blk & 1023, ph = sp >> 5, pw = sp & 31;
    int y0 = ph * 8 - 3, x0 = pw * 8 - 3;

    // ---- load halos ----
    for (int i = tid; i < 196; i += 512) {
        int hy = i / 14, hx = i - hy * 14;
        int gy = y0 + hy, gx = x0 + hx;
        s_idxI[i] = (gy >= 0 && gy < HH && gx >= 0 && gx < WW)
                  ? g_idx[b * HWSZ + gy * WW + gx] : -1;
    }
    for (int i = tid; i < 196 * 16; i += 512) {        // kv halo: 14x14 x 64ch
        int px = i >> 4, v = i & 15;
        int hy = px / 14, hx = px - hy * 14;
        int gy = y0 + hy, gx = x0 + hx;
        float4 val = make_float4(0.f, 0.f, 0.f, 0.f);
        if (gy >= 0 && gy < HH && gx >= 0 && gx < WW)
            val = *(const float4*)(g_pre + ((size_t)(b * HWSZ + gy * WW + gx)) * 96 + 32 + v * 4);
        *(float4*)(sm + OFF_KV + px * 64 + v * 4) = val;
    }
    for (int i = tid; i < 100 * 8; i += 512) {         // q halo: 10x10 x 32ch
        int px = i >> 3, v = i & 7;
        int hy = px / 10, hx = px - hy * 10;
        int gy = y0 + 2 + hy, gx = x0 + 2 + hx;
        float4 val = make_float4(0.f, 0.f, 0.f, 0.f);
        if (gy >= 0 && gy < HH && gx >= 0 && gx < WW)
            val = *(const float4*)(g_pre + ((size_t)(b * HWSZ + gy * WW + gx)) * 96 + v * 4);
        *(float4*)(sm + OFF_QT + px * 32 + v * 4) = val;
    }
    __syncthreads();

    // ---- per-expert masked convs ----
    for (int e = 0; e < 4; e++) {
        for (int i = tid; i < 3136; i += 512) sm[OFF_WKV + i] = kvdww[e * 3136 + i];
        if (tid < 288) sm[OFF_WQ + tid] = qdww[e * 288 + tid];
        if (tid < 64)  sm[OFF_BKV + tid] = kvdwb[e * 64 + tid];
        if (tid < 32)  sm[OFF_BQ + tid]  = qdwb[e * 32 + tid];
        for (int i = tid; i < 196; i += 512)
            sm[OFF_MASK + i] = (s_idxI[i] == e) ? 1.f : 0.f;
        __syncthreads();

        // 7x7 over kv halo: thread = (ch in 64, row in 8), 8 outputs
        {
            int ch = tid & 63, row = tid >> 6;
            float bv = sm[OFF_BKV + ch];
            float acc[8];
            #pragma unroll
            for (int j = 0; j < 8; j++) acc[j] = bv;
            #pragma unroll
            for (int ky = 0; ky < 7; ky++) {
                const float* kvrow = sm + OFF_KV + (row + ky) * 14 * 64 + ch;
                const float* mrow  = sm + OFF_MASK + (row + ky) * 14;
                float mv[14];
                #pragma unroll
                for (int xx = 0; xx < 14; xx++) mv[xx] = kvrow[xx * 64] * mrow[xx];
                const float* wr = sm + OFF_WKV + ch * 49 + ky * 7;
                #pragma unroll
                for (int kx = 0; kx < 7; kx++) {
                    float w = wr[kx];
                    #pragma unroll
                    for (int j = 0; j < 8; j++) acc[j] += w * mv[j + kx];
                }
            }
            if (ch < 32) {
                float* kd = sm + OFF_KE + (e * 32 + ch) * 65 + row * 8;
                #pragma unroll
                for (int j = 0; j < 8; j++) kd[j] = acc[j];
            } else {
                #pragma unroll
                for (int j = 0; j < 8; j++) {
                    int own = s_idxI[(row + 3) * 14 + (j + 3)];
                    if (own == e) sm[OFF_OUT + (row * 8 + j) * 64 + ch] = acc[j];
                }
            }
        }
        // 3x3 over q halo: threads 0..255 = (ch in 32, row in 8)
        if (tid < 256) {
            int ch = tid & 31, row = tid >> 5;
            float bv = sm[OFF_BQ + ch];
            float acc[8];
            #pragma unroll
            for (int j = 0; j < 8; j++) acc[j] = bv;
            #pragma unroll
            for (int ky = 0; ky < 3; ky++) {
                const float* qrow = sm + OFF_QT + (row + ky) * 10 * 32 + ch;
                const float* mrow = sm + OFF_MASK + (row + ky + 2) * 14 + 2;
                float mv[10];
                #pragma unroll
                for (int xx = 0; xx < 10; xx++) mv[xx] = qrow[xx * 32] * mrow[xx];
                const float* wr = sm + OFF_WQ + ch * 9 + ky * 3;
                #pragma unroll
                for (int kx = 0; kx < 3; kx++) {
                    float w = wr[kx];
                    #pragma unroll
                    for (int j = 0; j < 8; j++) acc[j] += w * mv[j + kx];
                }
            }
            float* qd = sm + OFF_QE + (e * 32 + ch) * 65 + row * 8;
            #pragma unroll
            for (int j = 0; j < 8; j++) qd[j] = acc[j];
        }
        __syncthreads();
    }

    // ---- circular conv per pixel with its owner's q,k ----
    {
        int ch = tid >> 4;            // 0..31
        int g4 = (tid & 15) * 4;      // 4 consecutive pixels
        #pragma unroll
        for (int pp = 0; pp < 4; pp++) {
            int px = g4 + pp;
            int i = px >> 3, j = px & 7;
            int e = s_idxI[(i + 3) * 14 + (j + 3)];
            const float* q = sm + OFF_QE + (e * 32 + ch) * 65;
            const float* k = sm + OFF_KE + (e * 32 + ch) * 65;
            float out = 0.f;
            #pragma unroll
            for (int a = 0; a < 8; a++) {
                const float* qa = q + a * 8;
                const float* ka = k + ((i - a) & 7) * 8;
                #pragma unroll
                for (int bb = 0; bb < 8; bb++)
                    out += qa[bb] * ka[(j - bb) & 7];
            }
            sm[OFF_OUT + px * 64 + ch] = out;
        }
    }
    __syncthreads();

    // ---- dense coalesced write of attn+v ----
    for (int i = tid; i < 64 * 16; i += 512) {
        int px = i >> 4, v = i & 15;
        int gi = px >> 3, gj = px & 7;
        size_t gp = (size_t)b * HWSZ + (ph * 8 + gi) * WW + (pw * 8 + gj);
        *(float4*)(g_av + gp * 64 + v * 4) = *(float4*)(sm + OFF_OUT + px * 64 + v * 4);
    }
}

// ---------------- D: LN, *v, fp, silu gate, p2, residual ----------------
__global__ __launch_bounds__(128) void k_D(const float* __restrict__ x,
                                           const float* __restrict__ sh,
                                           const float* __restrict__ fpw,
                                           const float* __restrict__ fpb,
                                           const float* __restrict__ p1w,
                                           const float* __restrict__ p2w,
                                           const float* __restrict__ lnw,
                                           const float* __restrict__ lnb) {
    extern __shared__ float smd[];  // per expert: fp 1024 | p1 2048 | p2 2048 | fpb/lnw/lnb 96 = 5216
    int tid = threadIdx.x;
    for (int i = tid; i < 4096; i += 128) smd[(i >> 10) * 5216 + (i & 1023)] = fpw[i];
    for (int i = tid; i < 8192; i += 128) smd[(i >> 11) * 5216 + 1024 + (i & 2047)] = p1w[i];
    for (int i = tid; i < 8192; i += 128) smd[(i >> 11) * 5216 + 3072 + (i & 2047)] = p2w[i];
    if (tid < 128) {
        smd[(tid >> 5) * 5216 + 5120 + (tid & 31)] = fpb[tid];
        smd[(tid >> 5) * 5216 + 5152 + (tid & 31)] = lnw[tid];
        smd[(tid >> 5) * 5216 + 5184 + (tid & 31)] = lnb[tid];
    }
    __syncthreads();

    int p = blockIdx.x * 128 + tid;
    int b = p >> 16, s = p & 0xFFFF;
    int e = g_idx[p];
    float m = g_gate[p];
    const float* base_ = smd + e * 5216;
    const float* s_fp  = base_;
    const float* s_p1  = base_ + 1024;
    const float* s_p2  = base_ + 3072;
    const float* s_fpb = base_ + 5120;
    const float* s_lnw = base_ + 5152;
    const float* s_lnb = base_ + 5184;

    float shv[64];
    const float* shb = sh + ((size_t)b * DIM) * HWSZ + s;
    #pragma unroll
    for (int c = 0; c < 64; c++) shv[c] = shb[(size_t)c * HWSZ];

    // attn + v, pixel-major contiguous
    const float* av = g_av + (size_t)p * 64;
    float t[32], vv[32];
    {
        #pragma unroll
        for (int j = 0; j < 8; j++) {
            float4 a4 = *(const float4*)(av + j * 4);
            t[4*j] = a4.x; t[4*j+1] = a4.y; t[4*j+2] = a4.z; t[4*j+3] = a4.w;
            float4 v4 = *(const float4*)(av + 32 + j * 4);
            vv[4*j] = v4.x; vv[4*j+1] = v4.y; vv[4*j+2] = v4.z; vv[4*j+3] = v4.w;
        }
    }
    float sum = 0.f, sq = 0.f;
    #pragma unroll
    for (int r = 0; r < 32; r++) { sum += t[r]; sq += t[r] * t[r]; }
    float mean = sum * (1.f / 32.f);
    float var  = sq * (1.f / 32.f) - mean * mean;
    float inv  = rsqrtf(var + 1e-5f);
    #pragma unroll
    for (int r = 0; r < 32; r++)
        t[r] = ((t[r] - mean) * inv * s_lnw[r] + s_lnb[r]) * vv[r];

    float bg[32];
    #pragma unroll 2
    for (int o = 0; o < 32; o++) {
        const float4* fr = (const float4*)(s_fp + o * 32);
        float acc = s_fpb[o];
        #pragma unroll
        for (int j = 0; j < 8; j++) {
            float4 w = fr[j];
            acc += w.x * t[4*j] + w.y * t[4*j+1] + w.z * t[4*j+2] + w.w * t[4*j+3];
        }
        const float4* pr = (const float4*)(s_p1 + o * 64);
        float g = 0.f;
        #pragma unroll
        for (int j = 0; j < 16; j++) {
            float4 w = pr[j];
            g += w.x * shv[4*j] + w.y * shv[4*j+1] + w.z * shv[4*j+2] + w.w * shv[4*j+3];
        }
        float z = m * g;
        float sg = z / (1.f + expf(-z));
        bg[o] = acc * sg;
    }

    const float* xb = x + ((size_t)b * DIM) * HWSZ + s;
    float* cb = g_comb + (size_t)p * 64;
    float m2 = m * m;
    #pragma unroll 2
    for (int og = 0; og < 16; og++) {
        float r[4];
        #pragma unroll
        for (int u = 0; u < 4; u++) {
            int oc = og * 4 + u;
            const float4* pr = (const float4*)(s_p2 + oc * 32);
            float acc = 0.f;
            #pragma unroll
            for (int j = 0; j < 8; j++) {
                float4 w = pr[j];
                acc += w.x * bg[4*j] + w.y * bg[4*j+1] + w.z * bg[4*j+2] + w.w * bg[4*j+3];
            }
            r[u] = m * acc + m2 * xb[(size_t)oc * HWSZ];
        }
        *(float4*)(cb + og * 4) = make_float4(r[0], r[1], r[2], r[3]);
    }
}

// ---------------- final 64x64 output conv ----------------
__global__ __launch_bounds__(128) void k_out(const float* __restrict__ ow,
                                             const float* __restrict__ ob,
                                             float* __restrict__ out) {
    __shared__ float sW[64 * 64];
    __shared__ float sB[64];
    int tid = threadIdx.x;
    for (int i = tid; i < 4096; i += 128) sW[i] = ow[i];
    if (tid < 64) sB[tid] = ob[tid];
    __syncthreads();
    int p = blockIdx.x * 128 + tid;
    int b = p >> 16, s = p & 0xFFFF;
    const float* cb = g_comb + (size_t)p * 64;
    float cv[64];
    #pragma unroll
    for (int j = 0; j < 16; j++) {
        float4 c4 = *(const float4*)(cb + j * 4);
        cv[4*j] = c4.x; cv[4*j+1] = c4.y; cv[4*j+2] = c4.z; cv[4*j+3] = c4.w;
    }
    float* ob_ = out + ((size_t)b * DIM) * HWSZ + s;
    #pragma unroll 2
    for (int o = 0; o < 64; o++) {
        const float4* wr = (const float4*)(sW + o * 64);
        float acc = sB[o];
        #pragma unroll
        for (int j = 0; j < 16; j++) {
            float4 w = wr[j];
            acc += w.x * cv[4*j] + w.y * cv[4*j+1] + w.z * cv[4*j+2] + w.w * cv[4*j+3];
        }
        ob_[(size_t)o * HWSZ] = acc;
    }
}

// ---------------- launch ----------------
extern "C" void kernel_launch(void* const* d_in, const int* in_sizes, int n_in,
                              void* d_out, int out_size) {
    const float* x     = (const float*)d_in[0];
    const float* sh    = (const float*)d_in[1];
    const float* rw    = (const float*)d_in[2];
    const float* rb    = (const float*)d_in[3];
    const float* p0w   = (const float*)d_in[4];
    const float* p1w   = (const float*)d_in[5];
    const float* p2w   = (const float*)d_in[6];
    const float* qw    = (const float*)d_in[7];
    const float* qdww  = (const float*)d_in[8];
    const float* qdwb  = (const float*)d_in[9];
    const float* kvw   = (const float*)d_in[10];
    const float* kvdww = (const float*)d_in[11];
    const float* kvdwb = (const float*)d_in[12];
    const float* lnw   = (const float*)d_in[13];
    const float* lnb   = (const float*)d_in[14];
    const float* fpw   = (const float*)d_in[15];
    const float* fpb   = (const float*)d_in[16];
    const float* outw  = (const float*)d_in[17];
    const float* outb  = (const float*)d_in[18];
    float* out = (float*)d_out;

    static int inited = 0;
    if (!inited) {
        cudaFuncSetAttribute(k_A, cudaFuncAttributeMaxDynamicSharedMemorySize, 4 * 6144 * 4);
        cudaFuncSetAttribute(k_B, cudaFuncAttributeMaxDynamicSharedMemorySize, SMEM_B_FLOATS * 4);
        cudaFuncSetAttribute(k_D, cudaFuncAttributeMaxDynamicSharedMemorySize, 4 * 5216 * 4);
        inited = 1;
    }

    k_router<<<NPIX / 256, 256>>>(x, rw, rb);
    k_prep<<<(4 * 96 * 64) / 256, 256>>>(qw, kvw, p0w);
    k_A<<<NPIX / 256, 256, 4 * 6144 * 4>>>(x);
    k_B<<<BB * 1024, 512, SMEM_B_FLOATS * 4>>>(qdww, qdwb, kvdww, kvdwb);
    k_D<<<NPIX / 128, 128, 4 * 5216 * 4>>>(x, sh, fpw, fpb, p1w, p2w, lnw, lnb);
    k_out<<<NPIX / 128, 128>>>(outw, outb, out);
}

// round 6
// speedup vs baseline: 4.4132x; 1.7905x over previous
#include <cuda_runtime.h>

// ---------------- problem constants ----------------
#define BB    4
#define DIM   64
#define RANK  32
#define EE    4
#define HH    256
#define WW    256
#define HWSZ  65536
#define NPIX  262144

// ---------------- device scratch ----------------
__device__ float g_gate[NPIX];
__device__ int   g_idx[NPIX];
__device__ float g_W[4 * 96 * 64];
__device__ float g_pre[(size_t)NPIX * 96];   // [p][0:32)=qpre, [32:96)=kvpre
__device__ float g_av [(size_t)NPIX * 64];   // [p][0:32)=attn, [32:64)=v

// ---------------- fold q_w@p0_w / kv_w@p0_w ----------------
__global__ void k_prep(const float* __restrict__ qw,
                       const float* __restrict__ kvw,
                       const float* __restrict__ p0) {
    int i = blockIdx.x * blockDim.x + threadIdx.x;     // < 4*6144
    int e = i / 6144;
    int rem = i - e * 6144;
    int o = rem >> 6, c = rem & 63;
    const float* p0e = p0 + e * 2048;
    float acc = 0.f;
    if (o < 32) {
        const float* qe = qw + e * 1024 + o * 32;
        #pragma unroll
        for (int r = 0; r < 32; r++) acc += qe[r] * p0e[r * 64 + c];
    } else {
        const float* ke = kvw + e * 2048 + (o - 32) * 32;
        #pragma unroll
        for (int r = 0; r < 32; r++) acc += ke[r] * p0e[r * 64 + c];
    }
    g_W[i] = acc;
}

// ---------------- AR: fused router + 1x1 conv -> g_pre ----------------
__global__ __launch_bounds__(256) void k_AR(const float* __restrict__ x,
                                            const float* __restrict__ rw,
                                            const float* __restrict__ rb) {
    extern __shared__ float sW[];     // 24576 W | 256 rw | 4 rb
    int tid = threadIdx.x;
    for (int i = tid; i < 24576; i += 256) sW[i] = g_W[i];
    if (tid < 256) sW[24576 + tid] = rw[tid];
    if (tid < 4)   sW[24832 + tid] = rb[tid];
    __syncthreads();

    int p = blockIdx.x * 256 + tid;
    int b = p >> 16, s = p & 0xFFFF;
    const float* xb = x + ((size_t)b * DIM) * HWSZ + s;
    float xv[64];
    #pragma unroll
    for (int c = 0; c < 64; c++) xv[c] = xb[(size_t)c * HWSZ];

    const float* srw = sW + 24576;
    float l0 = sW[24832], l1 = sW[24833], l2 = sW[24834], l3 = sW[24835];
    #pragma unroll
    for (int c = 0; c < 64; c++) {
        float v = xv[c];
        l0 += srw[c] * v; l1 += srw[64 + c] * v;
        l2 += srw[128 + c] * v; l3 += srw[192 + c] * v;
    }
    float lm = l0; int am = 0;
    if (l1 > lm) { lm = l1; am = 1; }
    if (l2 > lm) { lm = l2; am = 2; }
    if (l3 > lm) { lm = l3; am = 3; }
    float m = 1.0f / (expf(l0 - lm) + expf(l1 - lm) + expf(l2 - lm) + expf(l3 - lm));
    g_gate[p] = m;
    g_idx[p]  = am;

    #pragma unroll
    for (int c = 0; c < 64; c++) xv[c] *= m;

    const float4* Wv = (const float4*)(sW + am * 6144);
    float* op = g_pre + (size_t)p * 96;
    #pragma unroll 2
    for (int og = 0; og < 24; og++) {
        float r[4];
        #pragma unroll
        for (int u = 0; u < 4; u++) {
            const float4* wr = Wv + (og * 4 + u) * 16;
            float acc = 0.f;
            #pragma unroll
            for (int j = 0; j < 16; j++) {
                float4 w = wr[j];
                acc += w.x * xv[4*j] + w.y * xv[4*j+1] + w.z * xv[4*j+2] + w.w * xv[4*j+3];
            }
            r[u] = acc;
        }
        *(float4*)(op + og * 4) = make_float4(r[0], r[1], r[2], r[3]);
    }
}

// ---------------- B: fused masked dwconv(3,7) + patch circular conv ----------------
// smem float offsets
#define OFF_KV   0          // 196*64 = 12544
#define OFF_QT   12544      // 100*32 = 3200
#define OFF_QE   15744      // 4*2081 = 8324 (expert stride 2081 = 32*65+1, bank-safe)
#define OFF_KE   24068      // 4*2081 = 8324
#define OFF_OUT  32392      // 64*68  = 4352 (pixel stride 68, bank-safe)
#define OFF_W7   36744      // 4*64*49 = 12544
#define OFF_W3   49288      // 4*32*9  = 1152
#define OFF_B7   50440      // 256
#define OFF_B3   50696      // 128
#define OFF_IDX  50824      // 196 ints
#define SMEM_B_FLOATS 51020
#define ESTRIDE  2081

__global__ __launch_bounds__(512) void k_B(const float* __restrict__ qdww,
                                           const float* __restrict__ qdwb,
                                           const float* __restrict__ kvdww,
                                           const float* __restrict__ kvdwb) {
    extern __shared__ float sm[];
    int* sIdx = (int*)(sm + OFF_IDX);
    int tid = threadIdx.x;
    int blk = blockIdx.x;
    int b = blk >> 10, sp = blk & 1023, ph = sp >> 5, pw = sp & 31;
    int y0 = ph * 8 - 3, x0 = pw * 8 - 3;

    // ---- stage all weights once ----
    for (int i = tid; i < 12544; i += 512) sm[OFF_W7 + i] = kvdww[i];
    for (int i = tid; i < 1152;  i += 512) sm[OFF_W3 + i] = qdww[i];
    if (tid < 256) sm[OFF_B7 + tid] = kvdwb[tid];
    if (tid < 128) sm[OFF_B3 + tid] = qdwb[tid];

    // ---- halos ----
    for (int i = tid; i < 196; i += 512) {
        int hy = i / 14, hx = i - hy * 14;
        int gy = y0 + hy, gx = x0 + hx;
        sIdx[i] = (gy >= 0 && gy < HH && gx >= 0 && gx < WW)
                ? g_idx[b * HWSZ + gy * WW + gx] : -1;
    }
    for (int i = tid; i < 196 * 16; i += 512) {     // kv halo 14x14 x 64ch
        int px = i >> 4, v = i & 15;
        int hy = px / 14, hx = px - hy * 14;
        int gy = y0 + hy, gx = x0 + hx;
        float4 val = make_float4(0.f, 0.f, 0.f, 0.f);
        if (gy >= 0 && gy < HH && gx >= 0 && gx < WW)
            val = *(const float4*)(g_pre + ((size_t)(b * HWSZ + gy * WW + gx)) * 96 + 32 + v * 4);
        *(float4*)(sm + OFF_KV + px * 64 + v * 4) = val;
    }
    for (int i = tid; i < 100 * 8; i += 512) {      // q halo 10x10 x 32ch
        int px = i >> 3, v = i & 7;
        int hy = px / 10, hx = px - hy * 10;
        int gy = y0 + 2 + hy, gx = x0 + 2 + hx;
        float4 val = make_float4(0.f, 0.f, 0.f, 0.f);
        if (gy >= 0 && gy < HH && gx >= 0 && gx < WW)
            val = *(const float4*)(g_pre + ((size_t)(b * HWSZ + gy * WW + gx)) * 96 + v * 4);
        *(float4*)(sm + OFF_QT + px * 32 + v * 4) = val;
    }
    __syncthreads();

    // ---- dw7, all 4 experts in one pass: thread = (ch 0..63, row 0..7) ----
    {
        int ch = tid & 63, row = tid >> 6;
        float acc[4][8];
        #pragma unroll
        for (int e = 0; e < 4; e++) {
            float bv = sm[OFF_B7 + e * 64 + ch];
            #pragma unroll
            for (int j = 0; j < 8; j++) acc[e][j] = bv;
        }
        #pragma unroll
        for (int ky = 0; ky < 7; ky++) {
            const float* inr = sm + OFF_KV + (row + ky) * 896 + ch;
            const int*   owr = sIdx + (row + ky) * 14;
            float in[14]; int ow[14];
            #pragma unroll
            for (int xx = 0; xx < 14; xx++) { in[xx] = inr[xx * 64]; ow[xx] = owr[xx]; }
            #pragma unroll
            for (int e = 0; e < 4; e++) {
                float me[14];
                #pragma unroll
                for (int xx = 0; xx < 14; xx++) me[xx] = (ow[xx] == e) ? in[xx] : 0.f;
                const float* wr = sm + OFF_W7 + (e * 64 + ch) * 49 + ky * 7;
                #pragma unroll
                for (int kx = 0; kx < 7; kx++) {
                    float w = wr[kx];
                    #pragma unroll
                    for (int j = 0; j < 8; j++) acc[e][j] += w * me[j + kx];
                }
            }
        }
        if (ch < 32) {              // k channels -> expert tiles
            #pragma unroll
            for (int e = 0; e < 4; e++) {
                float* kd = sm + OFF_KE + e * ESTRIDE + ch * 65 + row * 8;
                #pragma unroll
                for (int j = 0; j < 8; j++) kd[j] = acc[e][j];
            }
        } else {                    // v channels -> OUT (owner-selected)
            #pragma unroll
            for (int j = 0; j < 8; j++) {
                int own = sIdx[(row + 3) * 14 + (j + 3)];
                float v = (own == 0) ? acc[0][j] : (own == 1) ? acc[1][j]
                        : (own == 2) ? acc[2][j] : acc[3][j];
                sm[OFF_OUT + (row * 8 + j) * 68 + ch] = v;
            }
        }
    }

    // ---- dw3, all 4 experts: threads 0..255 = (ch 0..31, row 0..7) ----
    if (tid < 256) {
        int ch = tid & 31, row = tid >> 5;
        float acc[4][8];
        #pragma unroll
        for (int e = 0; e < 4; e++) {
            float bv = sm[OFF_B3 + e * 32 + ch];
            #pragma unroll
            for (int j = 0; j < 8; j++) acc[e][j] = bv;
        }
        #pragma unroll
        for (int ky = 0; ky < 3; ky++) {
            const float* inr = sm + OFF_QT + (row + ky) * 320 + ch;
            const int*   owr = sIdx + (row + ky + 2) * 14 + 2;
            float in[10]; int ow[10];
            #pragma unroll
            for (int xx = 0; xx < 10; xx++) { in[xx] = inr[xx * 32]; ow[xx] = owr[xx]; }
            #pragma unroll
            for (int e = 0; e < 4; e++) {
                float me[10];
                #pragma unroll
                for (int xx = 0; xx < 10; xx++) me[xx] = (ow[xx] == e) ? in[xx] : 0.f;
                const float* wr = sm + OFF_W3 + (e * 32 + ch) * 9 + ky * 3;
                #pragma unroll
                for (int kx = 0; kx < 3; kx++) {
                    float w = wr[kx];
                    #pragma unroll
                    for (int j = 0; j < 8; j++) acc[e][j] += w * me[j + kx];
                }
            }
        }
        #pragma unroll
        for (int e = 0; e < 4; e++) {
            float* qd = sm + OFF_QE + e * ESTRIDE + ch * 65 + row * 8;
            #pragma unroll
            for (int j = 0; j < 8; j++) qd[j] = acc[e][j];
        }
    }
    __syncthreads();

    // ---- circular conv per pixel with owner's q,k ----
    {
        int ch = tid >> 4;
        int g4 = (tid & 15) * 4;
        #pragma unroll
        for (int pp = 0; pp < 4; pp++) {
            int px = g4 + pp;
            int i = px >> 3, j = px & 7;
            int e = sIdx[(i + 3) * 14 + (j + 3)];
            const float* q = sm + OFF_QE + e * ESTRIDE + ch * 65;
            const float* k = sm + OFF_KE + e * ESTRIDE + ch * 65;
            float out = 0.f;
            #pragma unroll
            for (int a = 0; a < 8; a++) {
                const float* qa = q + a * 8;
                const float* ka = k + ((i - a) & 7) * 8;
                #pragma unroll
                for (int bb = 0; bb < 8; bb++)
                    out += qa[bb] * ka[(j - bb) & 7];
            }
            sm[OFF_OUT + px * 68 + ch] = out;
        }
    }
    __syncthreads();

    // ---- dense write of attn+v ----
    for (int i = tid; i < 64 * 16; i += 512) {
        int px = i >> 4, v = i & 15;
        int gi = px >> 3, gj = px & 7;
        size_t gp = (size_t)b * HWSZ + (ph * 8 + gi) * WW + (pw * 8 + gj);
        *(float4*)(g_av + gp * 64 + v * 4) = *(float4*)(sm + OFF_OUT + px * 68 + v * 4);
    }
}

// ---------------- DO: LN, *v, fp, silu gate, p2, residual, out-conv ----------------
#define DO_OW  20864
#define DO_OB  24960
#define DO_SMEM 25024
__global__ __launch_bounds__(128) void k_DO(const float* __restrict__ x,
                                            const float* __restrict__ sh,
                                            const float* __restrict__ fpw,
                                            const float* __restrict__ fpb,
                                            const float* __restrict__ p1w,
                                            const float* __restrict__ p2w,
                                            const float* __restrict__ lnw,
                                            const float* __restrict__ lnb,
                                            const float* __restrict__ ow,
                                            const float* __restrict__ ob,
                                            float* __restrict__ out) {
    extern __shared__ float smd[];  // per-expert 5216: fp|p1|p2|fpb|lnw|lnb ; then ow 4096, ob 64
    int tid = threadIdx.x;
    for (int i = tid; i < 4096; i += 128) smd[(i >> 10) * 5216 + (i & 1023)] = fpw[i];
    for (int i = tid; i < 8192; i += 128) smd[(i >> 11) * 5216 + 1024 + (i & 2047)] = p1w[i];
    for (int i = tid; i < 8192; i += 128) smd[(i >> 11) * 5216 + 3072 + (i & 2047)] = p2w[i];
    if (tid < 128) {
        smd[(tid >> 5) * 5216 + 5120 + (tid & 31)] = fpb[tid];
        smd[(tid >> 5) * 5216 + 5152 + (tid & 31)] = lnw[tid];
        smd[(tid >> 5) * 5216 + 5184 + (tid & 31)] = lnb[tid];
    }
    for (int i = tid; i < 4096; i += 128) smd[DO_OW + i] = ow[i];
    if (tid < 64) smd[DO_OB + tid] = ob[tid];
    __syncthreads();

    int p = blockIdx.x * 128 + tid;
    int b = p >> 16, s = p & 0xFFFF;
    int e = g_idx[p];
    float m = g_gate[p];
    const float* base_ = smd + e * 5216;
    const float* s_fp  = base_;
    const float* s_p1  = base_ + 1024;
    const float* s_p2  = base_ + 3072;
    const float* s_fpb = base_ + 5120;
    const float* s_lnw = base_ + 5152;
    const float* s_lnb = base_ + 5184;

    // 1. gate dots from shared path
    float gg[32];
    {
        float shv[64];
        const float* shb = sh + ((size_t)b * DIM) * HWSZ + s;
        #pragma unroll
        for (int c = 0; c < 64; c++) shv[c] = shb[(size_t)c * HWSZ];
        #pragma unroll 2
        for (int o = 0; o < 32; o++) {
            const float4* pr = (const float4*)(s_p1 + o * 64);
            float g = 0.f;
            #pragma unroll
            for (int j = 0; j < 16; j++) {
                float4 w = pr[j];
                g += w.x * shv[4*j] + w.y * shv[4*j+1] + w.z * shv[4*j+2] + w.w * shv[4*j+3];
            }
            gg[o] = g;
        }
    }

    // 2. LN(attn) * v
    const float* av = g_av + (size_t)p * 64;
    float t[32], vv[32];
    #pragma unroll
    for (int j = 0; j < 8; j++) {
        float4 a4 = *(const float4*)(av + j * 4);
        t[4*j] = a4.x; t[4*j+1] = a4.y; t[4*j+2] = a4.z; t[4*j+3] = a4.w;
        float4 v4 = *(const float4*)(av + 32 + j * 4);
        vv[4*j] = v4.x; vv[4*j+1] = v4.y; vv[4*j+2] = v4.z; vv[4*j+3] = v4.w;
    }
    float sum = 0.f, sq = 0.f;
    #pragma unroll
    for (int r = 0; r < 32; r++) { sum += t[r]; sq += t[r] * t[r]; }
    float mean = sum * (1.f / 32.f);
    float var  = sq * (1.f / 32.f) - mean * mean;
    float inv  = rsqrtf(var + 1e-5f);
    #pragma unroll
    for (int r = 0; r < 32; r++)
        t[r] = ((t[r] - mean) * inv * s_lnw[r] + s_lnb[r]) * vv[r];

    // 3. body * silu gate
    float bg[32];
    #pragma unroll 2
    for (int o = 0; o < 32; o++) {
        const float4* fr = (const float4*)(s_fp + o * 32);
        float acc = s_fpb[o];
        #pragma unroll
        for (int j = 0; j < 8; j++) {
            float4 w = fr[j];
            acc += w.x * t[4*j] + w.y * t[4*j+1] + w.z * t[4*j+2] + w.w * t[4*j+3];
        }
        float z = m * gg[o];
        float sg = z / (1.f + expf(-z));
        bg[o] = acc * sg;
    }

    // 4. comb = m*(p2@bg) + m^2*x
    float comb[64];
    {
        const float* xb = x + ((size_t)b * DIM) * HWSZ + s;
        float m2 = m * m;
        #pragma unroll 2
        for (int oc = 0; oc < 64; oc++) {
            const float4* pr = (const float4*)(s_p2 + oc * 32);
            float acc = 0.f;
            #pragma unroll
            for (int j = 0; j < 8; j++) {
                float4 w = pr[j];
                acc += w.x * bg[4*j] + w.y * bg[4*j+1] + w.z * bg[4*j+2] + w.w * bg[4*j+3];
            }
            comb[oc] = m * acc + m2 * xb[(size_t)oc * HWSZ];
        }
    }

    // 5. out conv
    float* ob_ = out + ((size_t)b * DIM) * HWSZ + s;
    #pragma unroll 2
    for (int o = 0; o < 64; o++) {
        const float4* wr = (const float4*)(smd + DO_OW + o * 64);
        float acc = smd[DO_OB + o];
        #pragma unroll
        for (int j = 0; j < 16; j++) {
            float4 w = wr[j];
            acc += w.x * comb[4*j] + w.y * comb[4*j+1] + w.z * comb[4*j+2] + w.w * comb[4*j+3];
        }
        ob_[(size_t)o * HWSZ] = acc;
    }
}

// ---------------- launch ----------------
extern "C" void kernel_launch(void* const* d_in, const int* in_sizes, int n_in,
                              void* d_out, int out_size) {
    const float* x     = (const float*)d_in[0];
    const float* sh    = (const float*)d_in[1];
    const float* rw    = (const float*)d_in[2];
    const float* rb    = (const float*)d_in[3];
    const float* p0w   = (const float*)d_in[4];
    const float* p1w   = (const float*)d_in[5];
    const float* p2w   = (const float*)d_in[6];
    const float* qw    = (const float*)d_in[7];
    const float* qdww  = (const float*)d_in[8];
    const float* qdwb  = (const float*)d_in[9];
    const float* kvw   = (const float*)d_in[10];
    const float* kvdww = (const float*)d_in[11];
    const float* kvdwb = (const float*)d_in[12];
    const float* lnw   = (const float*)d_in[13];
    const float* lnb   = (const float*)d_in[14];
    const float* fpw   = (const float*)d_in[15];
    const float* fpb   = (const float*)d_in[16];
    const float* outw  = (const float*)d_in[17];
    const float* outb  = (const float*)d_in[18];
    float* out = (float*)d_out;

    static int inited = 0;
    if (!inited) {
        cudaFuncSetAttribute(k_AR, cudaFuncAttributeMaxDynamicSharedMemorySize, 24836 * 4);
        cudaFuncSetAttribute(k_B,  cudaFuncAttributeMaxDynamicSharedMemorySize, SMEM_B_FLOATS * 4);
        cudaFuncSetAttribute(k_DO, cudaFuncAttributeMaxDynamicSharedMemorySize, DO_SMEM * 4);
        inited = 1;
    }

    k_prep<<<(4 * 6144) / 256, 256>>>(qw, kvw, p0w);
    k_AR<<<NPIX / 256, 256, 24836 * 4>>>(x, rw, rb);
    k_B<<<BB * 1024, 512, SMEM_B_FLOATS * 4>>>(qdww, qdwb, kvdww, kvdwb);
    k_DO<<<NPIX / 128, 128, DO_SMEM * 4>>>(x, sh, fpw, fpb, p1w, p2w, lnw, lnb,
                                           outw, outb, out);
}